// round 14
// baseline (speedup 1.0000x reference)
#include <cuda_runtime.h>
#include <cuda_fp16.h>
#include <math.h>

// Problem constants
#define B_ 2
#define T_ 2048
#define D_ 1024
#define H_ 16
#define DH_ 64
#define NROW (B_ * T_)        // 4096
#define BH_ (B_ * H_)         // 32

// ---------------------------------------------------------------------------
// Scratch
// ---------------------------------------------------------------------------
__device__ __half g_xh [(size_t)NROW * D_];             // fp16 x
__device__ __half g_w1t[(size_t)(3 * D_) * D_];         // fp16 qkv_w transposed [N][K]
__device__ __half g_w2t[(size_t)D_ * D_];               // fp16 out_w transposed [N][K]
__device__ __half g_qh[(size_t)BH_ * T_ * DH_];
__device__ __half g_kh[(size_t)BH_ * T_ * DH_];
__device__ __half g_vh[(size_t)BH_ * T_ * DH_];
__device__ __half g_attnh[(size_t)NROW * D_];           // [4096, 1024] fp16
__device__ float2 g_rt[(size_t)T_ * 32];                // rope (cos,sin) table
// split-KV partials: [part(2)][pidx(256)][row(128)] x 64 cols f32 / (m,l)
__device__ float  g_po [(size_t)2 * 256 * 128 * 64];
__device__ float2 g_pml[(size_t)2 * 256 * 128];

// attention work schedule, sorted by descending tile count:
// {qt, kt0, kt1, mode}  mode: 0=direct, 1=partial part0, 2=partial part1
__constant__ int4 WORK[24] = {
    {15, 0, 16, 1}, {15, 16, 32, 2}, { 7, 0, 16, 0},
    {14, 0, 15, 1}, {14, 15, 30, 2},
    {13, 0, 14, 1}, {13, 14, 28, 2}, { 6, 0, 14, 0},
    {12, 0, 13, 1}, {12, 13, 26, 2},
    {11, 0, 12, 1}, {11, 12, 24, 2}, { 5, 0, 12, 0},
    {10, 0, 11, 1}, {10, 11, 22, 2},
    { 9, 0, 10, 1}, { 9, 10, 20, 2}, { 4, 0, 10, 0},
    { 8, 0,  9, 1}, { 8,  9, 18, 2},
    { 3, 0,  8, 0}, { 2, 0,  6, 0}, { 1, 0, 4, 0}, { 0, 0, 2, 0}
};

// ---------------------------------------------------------------------------
// helpers
// ---------------------------------------------------------------------------
__device__ __forceinline__ unsigned pack_h2(float a, float b) {
    __half2 h = __floats2half2_rn(a, b);
    return *(unsigned*)&h;
}
__device__ __forceinline__ void mma_f16(float* c,
                                        unsigned a0, unsigned a1, unsigned a2, unsigned a3,
                                        unsigned b0, unsigned b1) {
    asm volatile("mma.sync.aligned.m16n8k16.row.col.f32.f16.f16.f32 "
                 "{%0,%1,%2,%3}, {%4,%5,%6,%7}, {%8,%9}, {%0,%1,%2,%3};"
                 : "+f"(c[0]), "+f"(c[1]), "+f"(c[2]), "+f"(c[3])
                 : "r"(a0), "r"(a1), "r"(a2), "r"(a3), "r"(b0), "r"(b1));
}
__device__ __forceinline__ void cp16(void* smem, const void* gmem) {
    unsigned s = (unsigned)__cvta_generic_to_shared(smem);
    asm volatile("cp.async.cg.shared.global [%0], [%1], 16;" :: "r"(s), "l"(gmem));
}
__device__ __forceinline__ void cp_commit() { asm volatile("cp.async.commit_group;"); }
__device__ __forceinline__ void cp_wait0()  { asm volatile("cp.async.wait_group 0;"); }

__device__ __forceinline__ void ldsm_x4(unsigned& r0, unsigned& r1,
                                        unsigned& r2, unsigned& r3, const void* p) {
    unsigned s = (unsigned)__cvta_generic_to_shared(p);
    asm volatile("ldmatrix.sync.aligned.m8n8.x4.shared.b16 {%0,%1,%2,%3}, [%4];"
                 : "=r"(r0), "=r"(r1), "=r"(r2), "=r"(r3) : "r"(s));
}
__device__ __forceinline__ void ldsm_x4_trans(unsigned& r0, unsigned& r1,
                                              unsigned& r2, unsigned& r3, const void* p) {
    unsigned s = (unsigned)__cvta_generic_to_shared(p);
    asm volatile("ldmatrix.sync.aligned.m8n8.x4.trans.shared.b16 {%0,%1,%2,%3}, [%4];"
                 : "=r"(r0), "=r"(r1), "=r"(r2), "=r"(r3) : "r"(s));
}

// ---------------------------------------------------------------------------
// prep kernels
// ---------------------------------------------------------------------------
__global__ void to_half_kernel(const float* __restrict__ in, __half* __restrict__ out)
{
    const int i = (blockIdx.x * blockDim.x + threadIdx.x) * 4;
    float4 v = *(const float4*)(in + i);
    *(__half2*)&out[i]     = __floats2half2_rn(v.x, v.y);
    *(__half2*)&out[i + 2] = __floats2half2_rn(v.z, v.w);
}

// in f32 [K][N] -> out fp16 [N][K]
__global__ void transpose_to_half(const float* __restrict__ in, __half* __restrict__ out,
                                  int K, int N)
{
    __shared__ float tile[32][33];
    const int n0 = blockIdx.x * 32;
    const int k0 = blockIdx.y * 32;
    const int tx = threadIdx.x;
    const int ty = threadIdx.y;
#pragma unroll
    for (int j = 0; j < 4; j++)
        tile[ty + 8 * j][tx] = in[(size_t)(k0 + ty + 8 * j) * N + n0 + tx];
    __syncthreads();
#pragma unroll
    for (int j = 0; j < 4; j++)
        out[(size_t)(n0 + ty + 8 * j) * K + k0 + tx] = __float2half(tile[tx][ty + 8 * j]);
}

// rope table: g_rt[t*32 + d2] = (cos, sin) of t / 10000^(d2/32)
__global__ void rope_table_kernel()
{
    const int idx = blockIdx.x * blockDim.x + threadIdx.x;   // 0..65535
    const int t = idx >> 5;
    const int d2 = idx & 31;
    const float inv = __powf(10000.0f, -(float)d2 * (1.0f / 32.0f));
    float sn, cs;
    sincosf((float)t * inv, &sn, &cs);
    g_rt[idx] = make_float2(cs, sn);
}

// ---------------------------------------------------------------------------
// fp16 GEMM: block 128x128, BK=64, 128 threads = 4 warps (2m x 2n),
// warp tile 64x64. 2-stage cp.async (single barrier per ktile).
// mode 0: C(f32) = A@Bt + bias (out projection)
// mode 1: fused QKV epilogue — RoPE in registers, scatter q/k/v fp16.
// ---------------------------------------------------------------------------
#define GP 72
#define GEMM_SMEM (2 * (128 + 128) * GP * 2)

__global__ void __launch_bounds__(128, 2)
gemm_fp16(const __half* __restrict__ A, const __half* __restrict__ Bt,
          const float* __restrict__ bias, float* __restrict__ C,
          int mode, int M, int N, int K)
{
    extern __shared__ __half sh[];
    __half* Asm = sh;                    // [2][128][GP]
    __half* Bsm = sh + 2 * 128 * GP;     // [2][128][GP]

    const int bm = blockIdx.y * 128;
    const int bn = blockIdx.x * 128;
    const int tid = threadIdx.x;
    const int lane = tid & 31;
    const int w = tid >> 5;
    const int lrow = lane >> 2;
    const int lk = lane & 3;
    const int wm = (w & 1) * 64;
    const int wn = (w >> 1) * 64;

    const int a_row_off = lane & 15;
    const int a_col_off = (lane >> 4) * 8;
    const int b_row_off = (lane >> 4) * 8 + (lane & 7);
    const int b_col_off = ((lane >> 3) & 1) * 8;

    float acc[4][8][4];
#pragma unroll
    for (int mt = 0; mt < 4; mt++)
#pragma unroll
        for (int nt = 0; nt < 8; nt++)
#pragma unroll
            for (int i = 0; i < 4; i++) acc[mt][nt][i] = 0.0f;

    const int ntiles = K / 64;

    // prologue: stage tile 0
    {
#pragma unroll
        for (int i = 0; i < 8; i++) {
            const int e = tid + i * 128;
            const int r = e >> 3;
            const int c = (e & 7) * 8;
            cp16(&Asm[r * GP + c], A + (size_t)(bm + r) * K + c);
            cp16(&Bsm[r * GP + c], Bt + (size_t)(bn + r) * K + c);
        }
        cp_commit();
    }

    for (int t = 0; t < ntiles; t++) {
        const int s = t & 1;
        cp_wait0();
        __syncthreads();   // all warps done with buf s^1 (prev compute) + staging visible

        if (t + 1 < ntiles) {
            const int kn = (t + 1) * 64;
            __half* Ad = Asm + (s ^ 1) * 128 * GP;
            __half* Bd = Bsm + (s ^ 1) * 128 * GP;
#pragma unroll
            for (int i = 0; i < 8; i++) {
                const int e = tid + i * 128;
                const int r = e >> 3;
                const int c = (e & 7) * 8;
                cp16(&Ad[r * GP + c], A + (size_t)(bm + r) * K + kn + c);
                cp16(&Bd[r * GP + c], Bt + (size_t)(bn + r) * K + kn + c);
            }
            cp_commit();
        }

        const __half* Ah = Asm + s * 128 * GP;
        const __half* Bh = Bsm + s * 128 * GP;
#pragma unroll
        for (int kc = 0; kc < 4; kc++) {
            const int kh = kc * 16;
            unsigned af[4][4];
#pragma unroll
            for (int mt = 0; mt < 4; mt++)
                ldsm_x4(af[mt][0], af[mt][1], af[mt][2], af[mt][3],
                        &Ah[(wm + mt * 16 + a_row_off) * GP + kh + a_col_off]);
            unsigned bf[8][2];
#pragma unroll
            for (int ntp = 0; ntp < 4; ntp++) {
                unsigned r0, r1, r2, r3;
                ldsm_x4(r0, r1, r2, r3,
                        &Bh[(wn + ntp * 16 + b_row_off) * GP + kh + b_col_off]);
                bf[2 * ntp][0] = r0;     bf[2 * ntp][1] = r1;
                bf[2 * ntp + 1][0] = r2; bf[2 * ntp + 1][1] = r3;
            }
#pragma unroll
            for (int nt = 0; nt < 8; nt++)
#pragma unroll
                for (int mt = 0; mt < 4; mt++)
                    mma_f16(acc[mt][nt], af[mt][0], af[mt][1], af[mt][2], af[mt][3],
                            bf[nt][0], bf[nt][1]);
        }
        // NOTE: no end-of-loop __syncthreads — redundant with top-of-loop sync.
    }

    // ------------------------- epilogue -------------------------
    if (mode == 0) {
#pragma unroll
        for (int mt = 0; mt < 4; mt++) {
            const int row0 = bm + wm + mt * 16 + lrow;
#pragma unroll
            for (int nt = 0; nt < 8; nt++) {
                const int col = bn + wn + nt * 8 + lk * 2;
                const float bx = bias ? bias[col] : 0.f;
                const float by = bias ? bias[col + 1] : 0.f;
                *(float2*)&C[(size_t)row0 * N + col] =
                    make_float2(acc[mt][nt][0] + bx, acc[mt][nt][1] + by);
                *(float2*)&C[(size_t)(row0 + 8) * N + col] =
                    make_float2(acc[mt][nt][2] + bx, acc[mt][nt][3] + by);
            }
        }
        return;
    }

    // mode 1: fused RoPE + scatter.
    const int colbase = bn + wn;          // multiple of 64
    const int sec = colbase >> 10;        // 0=q, 1=k, 2=v
    const int h = (colbase >> 6) & (H_ - 1);

    if (sec == 2) {
#pragma unroll
        for (int mt = 0; mt < 4; mt++) {
            const int row0 = bm + wm + mt * 16 + lrow;
#pragma unroll
            for (int half = 0; half < 2; half++) {
                const int row = row0 + 8 * half;
                const int b = row >> 11;
                const int tt = row & (T_ - 1);
                const size_t base = ((size_t)(b * H_ + h) * T_ + tt) * DH_;
#pragma unroll
                for (int nt = 0; nt < 8; nt++) {
                    const int d = nt * 8 + lk * 2;
                    *(__half2*)&g_vh[base + d] =
                        __floats2half2_rn(acc[mt][nt][2 * half], acc[mt][nt][2 * half + 1]);
                }
            }
        }
    } else {
        __half* dst = (sec == 0) ? g_qh : g_kh;
        const float scale = (sec == 0) ? 0.125f : 1.0f;
#pragma unroll
        for (int mt = 0; mt < 4; mt++) {
            const int row0 = bm + wm + mt * 16 + lrow;
#pragma unroll
            for (int half = 0; half < 2; half++) {
                const int row = row0 + 8 * half;
                const int b = row >> 11;
                const int tt = row & (T_ - 1);
                const size_t base = ((size_t)(b * H_ + h) * T_ + tt) * DH_;
#pragma unroll
                for (int nt = 0; nt < 4; nt++) {
                    const int d = nt * 8 + lk * 2;
                    const float2 cs0 = g_rt[tt * 32 + d];
                    const float2 cs1 = g_rt[tt * 32 + d + 1];
                    const float a0 = acc[mt][nt][2 * half];
                    const float a1 = acc[mt][nt][2 * half + 1];
                    const float p0 = acc[mt][nt + 4][2 * half];
                    const float p1 = acc[mt][nt + 4][2 * half + 1];
                    const float lo0 = (a0 * cs0.x - p0 * cs0.y) * scale;
                    const float lo1 = (a1 * cs1.x - p1 * cs1.y) * scale;
                    const float hi0 = (p0 * cs0.x + a0 * cs0.y) * scale;
                    const float hi1 = (p1 * cs1.x + a1 * cs1.y) * scale;
                    *(__half2*)&dst[base + d]      = __floats2half2_rn(lo0, lo1);
                    *(__half2*)&dst[base + d + 32] = __floats2half2_rn(hi0, hi1);
                }
            }
        }
    }
}

// ---------------------------------------------------------------------------
// fp16 flash attention with split-KV. Block = WORK[blockIdx.x] x bh.
// mode 0: full range, normalized fp16 out. mode 1/2: half range, f32 partials.
// ---------------------------------------------------------------------------
#define AP 72
#define ATTN_SMEM ((128 * AP + 4 * 64 * AP) * 2)

__global__ void __launch_bounds__(128, 3)
attn_fp16_kernel()
{
    extern __shared__ __half sh[];
    __half* qs = sh;                         // [128][72]
    __half* kbuf[2] = { sh + 128 * AP, sh + 128 * AP + 2 * 64 * AP };
    __half* vbuf[2] = { sh + 128 * AP + 64 * AP, sh + 128 * AP + 3 * 64 * AP };

    const int4 wk = WORK[blockIdx.x];
    const int qt = wk.x;
    const int kt0 = wk.y;
    const int kt1 = wk.z;
    const int mode = wk.w;
    const int bh = blockIdx.y;
    const int tid = threadIdx.x;
    const int lane = tid & 31;
    const int w = tid >> 5;
    const int lrow = lane >> 2;
    const int lk = lane & 3;
    const int wrow = w * 32;

    const int a_row_off = lane & 15;
    const int a_col_off = (lane >> 4) * 8;
    const int b_row_off = (lane >> 4) * 8 + (lane & 7);
    const int b_col_off = ((lane >> 3) & 1) * 8;

    const __half* Qb = g_qh + ((size_t)bh * T_ + qt * 128) * DH_;
    const __half* Kb = g_kh + (size_t)bh * T_ * DH_;
    const __half* Vb = g_vh + (size_t)bh * T_ * DH_;

#pragma unroll
    for (int i = 0; i < 8; i++) {
        const int e = tid + i * 128;
        const int r = e >> 3;
        const int c = (e & 7) * 8;
        cp16(&qs[r * AP + c], &Qb[r * 64 + c]);
    }
#pragma unroll
    for (int i = 0; i < 4; i++) {
        const int e = tid + i * 128;
        const int r = e >> 3;
        const int c = (e & 7) * 8;
        cp16(&kbuf[0][r * AP + c], Kb + (size_t)(kt0 * 64 + r) * 64 + c);
        cp16(&vbuf[0][r * AP + c], Vb + (size_t)(kt0 * 64 + r) * 64 + c);
    }
    cp_commit();

    float m[2][2], l[2][2];
    float oacc[2][8][4];
#pragma unroll
    for (int mg = 0; mg < 2; mg++) {
        m[mg][0] = -1e30f; m[mg][1] = -1e30f;
        l[mg][0] = 0.f;    l[mg][1] = 0.f;
#pragma unroll
        for (int nt = 0; nt < 8; nt++)
#pragma unroll
            for (int i = 0; i < 4; i++) oacc[mg][nt][i] = 0.f;
    }

    for (int kt = kt0; kt < kt1; kt++) {
        const int s = (kt - kt0) & 1;
        cp_wait0();
        __syncthreads();

        if (kt + 1 < kt1) {
#pragma unroll
            for (int i = 0; i < 4; i++) {
                const int e = tid + i * 128;
                const int r = e >> 3;
                const int c = (e & 7) * 8;
                cp16(&kbuf[s ^ 1][r * AP + c], Kb + (size_t)((kt + 1) * 64 + r) * 64 + c);
                cp16(&vbuf[s ^ 1][r * AP + c], Vb + (size_t)((kt + 1) * 64 + r) * 64 + c);
            }
            cp_commit();
        }

        const __half* ks = kbuf[s];
        const __half* vs = vbuf[s];

        float sacc[2][8][4];
#pragma unroll
        for (int mg = 0; mg < 2; mg++)
#pragma unroll
            for (int nt = 0; nt < 8; nt++)
#pragma unroll
                for (int i = 0; i < 4; i++) sacc[mg][nt][i] = 0.f;

#pragma unroll
        for (int kc = 0; kc < 4; kc++) {
            const int kh = kc * 16;
            unsigned af[2][4];
#pragma unroll
            for (int mg = 0; mg < 2; mg++)
                ldsm_x4(af[mg][0], af[mg][1], af[mg][2], af[mg][3],
                        &qs[(wrow + mg * 16 + a_row_off) * AP + kh + a_col_off]);
            unsigned bf[8][2];
#pragma unroll
            for (int ntp = 0; ntp < 4; ntp++) {
                unsigned r0, r1, r2, r3;
                ldsm_x4(r0, r1, r2, r3,
                        &ks[(ntp * 16 + b_row_off) * AP + kh + b_col_off]);
                bf[2 * ntp][0] = r0;     bf[2 * ntp][1] = r1;
                bf[2 * ntp + 1][0] = r2; bf[2 * ntp + 1][1] = r3;
            }
#pragma unroll
            for (int nt = 0; nt < 8; nt++)
#pragma unroll
                for (int mg = 0; mg < 2; mg++)
                    mma_f16(sacc[mg][nt], af[mg][0], af[mg][1], af[mg][2], af[mg][3],
                            bf[nt][0], bf[nt][1]);
        }

        if (kt * 64 + 63 > qt * 128 + wrow) {
#pragma unroll
            for (int mg = 0; mg < 2; mg++) {
                const int rg0 = qt * 128 + wrow + mg * 16 + lrow;
                const int rg1 = rg0 + 8;
#pragma unroll
                for (int nt = 0; nt < 8; nt++) {
                    const int cg = kt * 64 + nt * 8 + lk * 2;
                    if (cg > rg0)     sacc[mg][nt][0] = -1e30f;
                    if (cg + 1 > rg0) sacc[mg][nt][1] = -1e30f;
                    if (cg > rg1)     sacc[mg][nt][2] = -1e30f;
                    if (cg + 1 > rg1) sacc[mg][nt][3] = -1e30f;
                }
            }
        }

        unsigned pk01[2][8], pk23[2][8];
#pragma unroll
        for (int mg = 0; mg < 2; mg++) {
            float tm0 = -1e30f, tm1 = -1e30f;
#pragma unroll
            for (int nt = 0; nt < 8; nt++) {
                tm0 = fmaxf(tm0, fmaxf(sacc[mg][nt][0], sacc[mg][nt][1]));
                tm1 = fmaxf(tm1, fmaxf(sacc[mg][nt][2], sacc[mg][nt][3]));
            }
            tm0 = fmaxf(tm0, __shfl_xor_sync(0xffffffffu, tm0, 1));
            tm0 = fmaxf(tm0, __shfl_xor_sync(0xffffffffu, tm0, 2));
            tm1 = fmaxf(tm1, __shfl_xor_sync(0xffffffffu, tm1, 1));
            tm1 = fmaxf(tm1, __shfl_xor_sync(0xffffffffu, tm1, 2));

            const float mn0 = fmaxf(m[mg][0], tm0);
            const float mn1 = fmaxf(m[mg][1], tm1);
            const float corr0 = __expf(m[mg][0] - mn0);
            const float corr1 = __expf(m[mg][1] - mn1);
            m[mg][0] = mn0; m[mg][1] = mn1;

            float sum0 = 0.f, sum1 = 0.f;
#pragma unroll
            for (int nt = 0; nt < 8; nt++) {
                const float p00 = __expf(sacc[mg][nt][0] - mn0);
                const float p01 = __expf(sacc[mg][nt][1] - mn0);
                const float p10 = __expf(sacc[mg][nt][2] - mn1);
                const float p11 = __expf(sacc[mg][nt][3] - mn1);
                sum0 += p00 + p01;
                sum1 += p10 + p11;
                pk01[mg][nt] = pack_h2(p00, p01);
                pk23[mg][nt] = pack_h2(p10, p11);
            }
            sum0 += __shfl_xor_sync(0xffffffffu, sum0, 1);
            sum0 += __shfl_xor_sync(0xffffffffu, sum0, 2);
            sum1 += __shfl_xor_sync(0xffffffffu, sum1, 1);
            sum1 += __shfl_xor_sync(0xffffffffu, sum1, 2);
            l[mg][0] = l[mg][0] * corr0 + sum0;
            l[mg][1] = l[mg][1] * corr1 + sum1;

#pragma unroll
            for (int nt = 0; nt < 8; nt++) {
                oacc[mg][nt][0] *= corr0;
                oacc[mg][nt][1] *= corr0;
                oacc[mg][nt][2] *= corr1;
                oacc[mg][nt][3] *= corr1;
            }
        }

#pragma unroll
        for (int kc = 0; kc < 4; kc++) {
            const int g = lane >> 3;
            const int li = lane & 7;
            const int vrow = kc * 16 + (g & 1) * 8 + li;
#pragma unroll
            for (int ntp = 0; ntp < 4; ntp++) {
                const int vcol = ntp * 16 + (g >> 1) * 8;
                unsigned r0, r1, r2, r3;
                ldsm_x4_trans(r0, r1, r2, r3, &vs[vrow * AP + vcol]);
#pragma unroll
                for (int mg = 0; mg < 2; mg++) {
                    mma_f16(oacc[mg][ntp * 2],
                            pk01[mg][2 * kc], pk23[mg][2 * kc],
                            pk01[mg][2 * kc + 1], pk23[mg][2 * kc + 1], r0, r1);
                    mma_f16(oacc[mg][ntp * 2 + 1],
                            pk01[mg][2 * kc], pk23[mg][2 * kc],
                            pk01[mg][2 * kc + 1], pk23[mg][2 * kc + 1], r2, r3);
                }
            }
        }
    }

    if (mode == 0) {
        const int b = bh >> 4;
        const int h = bh & (H_ - 1);
#pragma unroll
        for (int mg = 0; mg < 2; mg++) {
            const float il0 = 1.0f / l[mg][0];
            const float il1 = 1.0f / l[mg][1];
            const int t0 = qt * 128 + wrow + mg * 16 + lrow;
            const int t1 = t0 + 8;
            const size_t base0 = ((size_t)(b * T_ + t0)) * D_ + h * DH_;
            const size_t base1 = ((size_t)(b * T_ + t1)) * D_ + h * DH_;
#pragma unroll
            for (int nt = 0; nt < 8; nt++) {
                const int c0 = nt * 8 + lk * 2;
                *(__half2*)&g_attnh[base0 + c0] =
                    __floats2half2_rn(oacc[mg][nt][0] * il0, oacc[mg][nt][1] * il0);
                *(__half2*)&g_attnh[base1 + c0] =
                    __floats2half2_rn(oacc[mg][nt][2] * il1, oacc[mg][nt][3] * il1);
            }
        }
    } else {
        const int part = mode - 1;
        const int pidx = (part * 256) + (qt - 8) * 32 + bh;
        float* po = g_po + (size_t)pidx * 128 * 64;
        float2* pml = g_pml + (size_t)pidx * 128;
#pragma unroll
        for (int mg = 0; mg < 2; mg++) {
#pragma unroll
            for (int half = 0; half < 2; half++) {
                const int row = wrow + mg * 16 + lrow + 8 * half;
#pragma unroll
                for (int nt = 0; nt < 8; nt++) {
                    const int c0 = nt * 8 + lk * 2;
                    *(float2*)&po[row * 64 + c0] =
                        make_float2(oacc[mg][nt][2 * half], oacc[mg][nt][2 * half + 1]);
                }
                if (lk == 0)
                    pml[row] = make_float2(m[mg][half], l[mg][half]);
            }
        }
    }
}

// ---------------------------------------------------------------------------
// split-KV merge: combine two partials per (qt>=8, bh), write fp16 attn out.
// grid (8, 32), 128 threads (one row each).
// ---------------------------------------------------------------------------
__global__ void attn_merge_kernel()
{
    const int p8 = blockIdx.x;            // 0..7 -> qt = p8+8
    const int bh = blockIdx.y;
    const int qt = p8 + 8;
    const int r = threadIdx.x;            // 0..127
    const int pidx = p8 * 32 + bh;

    const float2 ml1 = g_pml[(size_t)pidx * 128 + r];
    const float2 ml2 = g_pml[(size_t)(256 + pidx) * 128 + r];
    const float mm = fmaxf(ml1.x, ml2.x);
    const float a1 = __expf(ml1.x - mm);
    const float a2 = __expf(ml2.x - mm);
    const float il = 1.0f / (a1 * ml1.y + a2 * ml2.y);

    const float* o1 = g_po + (size_t)pidx * 128 * 64 + r * 64;
    const float* o2 = g_po + (size_t)(256 + pidx) * 128 * 64 + r * 64;
    const int b = bh >> 4;
    const int h = bh & (H_ - 1);
    const int trow = qt * 128 + r;
    __half* dst = g_attnh + ((size_t)(b * T_ + trow)) * D_ + h * DH_;

#pragma unroll
    for (int c = 0; c < 64; c += 2) {
        float2 v1 = *(const float2*)&o1[c];
        float2 v2 = *(const float2*)&o2[c];
        *(__half2*)&dst[c] = __floats2half2_rn((a1 * v1.x + a2 * v2.x) * il,
                                               (a1 * v1.y + a2 * v2.y) * il);
    }
}

// ---------------------------------------------------------------------------
// kernel_launch
// ---------------------------------------------------------------------------
extern "C" void kernel_launch(void* const* d_in, const int* in_sizes, int n_in,
                              void* d_out, int out_size)
{
    (void)in_sizes; (void)n_in; (void)out_size;
    const float* x     = (const float*)d_in[0];
    const float* qkv_w = (const float*)d_in[2];
    const float* out_w = (const float*)d_in[3];
    const float* out_b = (const float*)d_in[4];
    float* out = (float*)d_out;

    void *p_xh, *p_w1t, *p_w2t, *p_attnh;
    cudaGetSymbolAddress(&p_xh, g_xh);
    cudaGetSymbolAddress(&p_w1t, g_w1t);
    cudaGetSymbolAddress(&p_w2t, g_w2t);
    cudaGetSymbolAddress(&p_attnh, g_attnh);

    cudaFuncSetAttribute(gemm_fp16,
                         cudaFuncAttributeMaxDynamicSharedMemorySize, GEMM_SMEM);
    cudaFuncSetAttribute(attn_fp16_kernel,
                         cudaFuncAttributeMaxDynamicSharedMemorySize, ATTN_SMEM);

    // 0) prep
    to_half_kernel<<<(NROW * D_) / 1024, 256>>>(x, (__half*)p_xh);
    transpose_to_half<<<dim3(3 * D_ / 32, D_ / 32), dim3(32, 8)>>>(
        qkv_w, (__half*)p_w1t, D_, 3 * D_);
    transpose_to_half<<<dim3(D_ / 32, D_ / 32), dim3(32, 8)>>>(
        out_w, (__half*)p_w2t, D_, D_);
    rope_table_kernel<<<(T_ * 32) / 256, 256>>>();

    // 1) QKV projection with fused RoPE + scatter (mode 1)
    gemm_fp16<<<dim3((3 * D_) / 128, NROW / 128), 128, GEMM_SMEM>>>(
        (const __half*)p_xh, (const __half*)p_w1t, nullptr, nullptr,
        1, NROW, 3 * D_, D_);

    // 2) causal flash attention (split-KV, 24 work items x 32 bh)
    attn_fp16_kernel<<<dim3(24, BH_), 128, ATTN_SMEM>>>();

    // 2b) merge split-KV partials (qt >= 8)
    attn_merge_kernel<<<dim3(8, BH_), 128>>>();

    // 3) output projection + bias -> f32 (mode 0)
    gemm_fp16<<<dim3(D_ / 128, NROW / 128), 128, GEMM_SMEM>>>(
        (const __half*)p_attnh, (const __half*)p_w2t, out_b, out,
        0, NROW, D_, D_);
}

// round 15
// speedup vs baseline: 1.0775x; 1.0775x over previous
#include <cuda_runtime.h>
#include <cuda_fp16.h>
#include <math.h>

// Problem constants
#define B_ 2
#define T_ 2048
#define D_ 1024
#define H_ 16
#define DH_ 64
#define NROW (B_ * T_)        // 4096
#define BH_ (B_ * H_)         // 32

// ---------------------------------------------------------------------------
// Scratch
// ---------------------------------------------------------------------------
__device__ __half g_xh [(size_t)NROW * D_];             // fp16 x
__device__ __half g_w1t[(size_t)(3 * D_) * D_];         // fp16 qkv_w transposed [N][K]
__device__ __half g_w2t[(size_t)D_ * D_];               // fp16 out_w transposed [N][K]
__device__ __half g_qh[(size_t)BH_ * T_ * DH_];
__device__ __half g_kh[(size_t)BH_ * T_ * DH_];
__device__ __half g_vh[(size_t)BH_ * T_ * DH_];
__device__ __half g_attnh[(size_t)NROW * D_];           // [4096, 1024] fp16
__device__ float2 g_rt[(size_t)T_ * 32];                // rope (cos,sin) table

// ---------------------------------------------------------------------------
// helpers
// ---------------------------------------------------------------------------
__device__ __forceinline__ unsigned pack_h2(float a, float b) {
    __half2 h = __floats2half2_rn(a, b);
    return *(unsigned*)&h;
}
__device__ __forceinline__ void mma_f16(float* c,
                                        unsigned a0, unsigned a1, unsigned a2, unsigned a3,
                                        unsigned b0, unsigned b1) {
    asm volatile("mma.sync.aligned.m16n8k16.row.col.f32.f16.f16.f32 "
                 "{%0,%1,%2,%3}, {%4,%5,%6,%7}, {%8,%9}, {%0,%1,%2,%3};"
                 : "+f"(c[0]), "+f"(c[1]), "+f"(c[2]), "+f"(c[3])
                 : "r"(a0), "r"(a1), "r"(a2), "r"(a3), "r"(b0), "r"(b1));
}
__device__ __forceinline__ void cp16(void* smem, const void* gmem) {
    unsigned s = (unsigned)__cvta_generic_to_shared(smem);
    asm volatile("cp.async.cg.shared.global [%0], [%1], 16;" :: "r"(s), "l"(gmem));
}
__device__ __forceinline__ void cp_commit() { asm volatile("cp.async.commit_group;"); }
__device__ __forceinline__ void cp_wait0()  { asm volatile("cp.async.wait_group 0;"); }

__device__ __forceinline__ void ldsm_x4(unsigned& r0, unsigned& r1,
                                        unsigned& r2, unsigned& r3, const void* p) {
    unsigned s = (unsigned)__cvta_generic_to_shared(p);
    asm volatile("ldmatrix.sync.aligned.m8n8.x4.shared.b16 {%0,%1,%2,%3}, [%4];"
                 : "=r"(r0), "=r"(r1), "=r"(r2), "=r"(r3) : "r"(s));
}
__device__ __forceinline__ void ldsm_x4_trans(unsigned& r0, unsigned& r1,
                                              unsigned& r2, unsigned& r3, const void* p) {
    unsigned s = (unsigned)__cvta_generic_to_shared(p);
    asm volatile("ldmatrix.sync.aligned.m8n8.x4.trans.shared.b16 {%0,%1,%2,%3}, [%4];"
                 : "=r"(r0), "=r"(r1), "=r"(r2), "=r"(r3) : "r"(s));
}

// ---------------------------------------------------------------------------
// fused prep kernel — one launch covers:
//   blocks [0, 4096)        : x f32 -> fp16            (1024 elems/block)
//   blocks [4096, 7168)     : qkv_w [K][N] -> w1t [N][K] fp16 (32x32 tiles)
//   blocks [7168, 8192)     : out_w -> w2t
//   blocks [8192, 8448)     : rope table
// all blocks 256 threads.
// ---------------------------------------------------------------------------
#define PREP_BLOCKS (4096 + 3072 + 1024 + 256)

__global__ void prep_kernel(const float* __restrict__ x,
                            const float* __restrict__ w1,
                            const float* __restrict__ w2)
{
    __shared__ float tile[32][33];
    const int bid = blockIdx.x;
    const int tid = threadIdx.x;

    if (bid < 4096) {
        const int i = (bid * 256 + tid) * 4;
        float4 v = *(const float4*)(x + i);
        *(__half2*)&g_xh[i]     = __floats2half2_rn(v.x, v.y);
        *(__half2*)&g_xh[i + 2] = __floats2half2_rn(v.z, v.w);
    } else if (bid < 8192) {
        const float* in;
        __half* out;
        int bx, by, N;
        if (bid < 7168) {                     // w1: N=3072, K=1024; 96 x 32 tiles
            const int b = bid - 4096;
            bx = b % 96; by = b / 96; in = w1; out = g_w1t; N = 3 * D_;
        } else {                              // w2: N=1024, K=1024; 32 x 32 tiles
            const int b = bid - 7168;
            bx = b % 32; by = b / 32; in = w2; out = g_w2t; N = D_;
        }
        const int K = D_;
        const int n0 = bx * 32;
        const int k0 = by * 32;
        const int tx = tid & 31;
        const int ty = tid >> 5;              // 0..7
#pragma unroll
        for (int j = 0; j < 4; j++)
            tile[ty + 8 * j][tx] = in[(size_t)(k0 + ty + 8 * j) * N + n0 + tx];
        __syncthreads();
#pragma unroll
        for (int j = 0; j < 4; j++)
            out[(size_t)(n0 + ty + 8 * j) * K + k0 + tx] =
                __float2half(tile[tx][ty + 8 * j]);
    } else {
        const int idx = (bid - 8192) * 256 + tid;    // 0..65535
        const int t = idx >> 5;
        const int d2 = idx & 31;
        const float inv = __powf(10000.0f, -(float)d2 * (1.0f / 32.0f));
        float sn, cs;
        sincosf((float)t * inv, &sn, &cs);
        g_rt[idx] = make_float2(cs, sn);
    }
}

// ---------------------------------------------------------------------------
// fp16 GEMM: block 128x128, BK=64, 128 threads = 4 warps (2m x 2n),
// warp tile 64x64. 2-stage cp.async, single barrier per ktile.
// mode 0: C(f32) = A@Bt + bias (out projection)
// mode 1: fused QKV epilogue — RoPE in registers, scatter q/k/v fp16.
// ---------------------------------------------------------------------------
#define GP 72
#define GEMM_SMEM (2 * (128 + 128) * GP * 2)

__global__ void __launch_bounds__(128, 2)
gemm_fp16(const __half* __restrict__ A, const __half* __restrict__ Bt,
          const float* __restrict__ bias, float* __restrict__ C,
          int mode, int M, int N, int K)
{
    extern __shared__ __half sh[];
    __half* Asm = sh;                    // [2][128][GP]
    __half* Bsm = sh + 2 * 128 * GP;     // [2][128][GP]

    const int bm = blockIdx.y * 128;
    const int bn = blockIdx.x * 128;
    const int tid = threadIdx.x;
    const int lane = tid & 31;
    const int w = tid >> 5;
    const int lrow = lane >> 2;
    const int lk = lane & 3;
    const int wm = (w & 1) * 64;
    const int wn = (w >> 1) * 64;

    const int a_row_off = lane & 15;
    const int a_col_off = (lane >> 4) * 8;
    const int b_row_off = (lane >> 4) * 8 + (lane & 7);
    const int b_col_off = ((lane >> 3) & 1) * 8;

    float acc[4][8][4];
#pragma unroll
    for (int mt = 0; mt < 4; mt++)
#pragma unroll
        for (int nt = 0; nt < 8; nt++)
#pragma unroll
            for (int i = 0; i < 4; i++) acc[mt][nt][i] = 0.0f;

    const int ntiles = K / 64;

    // prologue: stage tile 0
    {
#pragma unroll
        for (int i = 0; i < 8; i++) {
            const int e = tid + i * 128;
            const int r = e >> 3;
            const int c = (e & 7) * 8;
            cp16(&Asm[r * GP + c], A + (size_t)(bm + r) * K + c);
            cp16(&Bsm[r * GP + c], Bt + (size_t)(bn + r) * K + c);
        }
        cp_commit();
    }

    for (int t = 0; t < ntiles; t++) {
        const int s = t & 1;
        cp_wait0();
        __syncthreads();   // orders prev compute of buf s^1 before restaging it

        if (t + 1 < ntiles) {
            const int kn = (t + 1) * 64;
            __half* Ad = Asm + (s ^ 1) * 128 * GP;
            __half* Bd = Bsm + (s ^ 1) * 128 * GP;
#pragma unroll
            for (int i = 0; i < 8; i++) {
                const int e = tid + i * 128;
                const int r = e >> 3;
                const int c = (e & 7) * 8;
                cp16(&Ad[r * GP + c], A + (size_t)(bm + r) * K + kn + c);
                cp16(&Bd[r * GP + c], Bt + (size_t)(bn + r) * K + kn + c);
            }
            cp_commit();
        }

        const __half* Ah = Asm + s * 128 * GP;
        const __half* Bh = Bsm + s * 128 * GP;
#pragma unroll
        for (int kc = 0; kc < 4; kc++) {
            const int kh = kc * 16;
            unsigned af[4][4];
#pragma unroll
            for (int mt = 0; mt < 4; mt++)
                ldsm_x4(af[mt][0], af[mt][1], af[mt][2], af[mt][3],
                        &Ah[(wm + mt * 16 + a_row_off) * GP + kh + a_col_off]);
            unsigned bf[8][2];
#pragma unroll
            for (int ntp = 0; ntp < 4; ntp++) {
                unsigned r0, r1, r2, r3;
                ldsm_x4(r0, r1, r2, r3,
                        &Bh[(wn + ntp * 16 + b_row_off) * GP + kh + b_col_off]);
                bf[2 * ntp][0] = r0;     bf[2 * ntp][1] = r1;
                bf[2 * ntp + 1][0] = r2; bf[2 * ntp + 1][1] = r3;
            }
#pragma unroll
            for (int nt = 0; nt < 8; nt++)
#pragma unroll
                for (int mt = 0; mt < 4; mt++)
                    mma_f16(acc[mt][nt], af[mt][0], af[mt][1], af[mt][2], af[mt][3],
                            bf[nt][0], bf[nt][1]);
        }
        // no end-of-loop sync (redundant with top-of-loop sync)
    }

    // ------------------------- epilogue -------------------------
    if (mode == 0) {
#pragma unroll
        for (int mt = 0; mt < 4; mt++) {
            const int row0 = bm + wm + mt * 16 + lrow;
#pragma unroll
            for (int nt = 0; nt < 8; nt++) {
                const int col = bn + wn + nt * 8 + lk * 2;
                const float bx = bias ? bias[col] : 0.f;
                const float by = bias ? bias[col + 1] : 0.f;
                *(float2*)&C[(size_t)row0 * N + col] =
                    make_float2(acc[mt][nt][0] + bx, acc[mt][nt][1] + by);
                *(float2*)&C[(size_t)(row0 + 8) * N + col] =
                    make_float2(acc[mt][nt][2] + bx, acc[mt][nt][3] + by);
            }
        }
        return;
    }

    // mode 1: fused RoPE + scatter. Warp tile covers exactly one (s,h).
    const int colbase = bn + wn;          // multiple of 64
    const int sec = colbase >> 10;        // 0=q, 1=k, 2=v
    const int h = (colbase >> 6) & (H_ - 1);

    if (sec == 2) {
#pragma unroll
        for (int mt = 0; mt < 4; mt++) {
            const int row0 = bm + wm + mt * 16 + lrow;
#pragma unroll
            for (int half = 0; half < 2; half++) {
                const int row = row0 + 8 * half;
                const int b = row >> 11;
                const int tt = row & (T_ - 1);
                const size_t base = ((size_t)(b * H_ + h) * T_ + tt) * DH_;
#pragma unroll
                for (int nt = 0; nt < 8; nt++) {
                    const int d = nt * 8 + lk * 2;
                    *(__half2*)&g_vh[base + d] =
                        __floats2half2_rn(acc[mt][nt][2 * half], acc[mt][nt][2 * half + 1]);
                }
            }
        }
    } else {
        __half* dst = (sec == 0) ? g_qh : g_kh;
        const float scale = (sec == 0) ? 0.125f : 1.0f;
#pragma unroll
        for (int mt = 0; mt < 4; mt++) {
            const int row0 = bm + wm + mt * 16 + lrow;
#pragma unroll
            for (int half = 0; half < 2; half++) {
                const int row = row0 + 8 * half;
                const int b = row >> 11;
                const int tt = row & (T_ - 1);
                const size_t base = ((size_t)(b * H_ + h) * T_ + tt) * DH_;
#pragma unroll
                for (int nt = 0; nt < 4; nt++) {
                    const int d = nt * 8 + lk * 2;
                    const float2 cs0 = g_rt[tt * 32 + d];
                    const float2 cs1 = g_rt[tt * 32 + d + 1];
                    const float a0 = acc[mt][nt][2 * half];
                    const float a1 = acc[mt][nt][2 * half + 1];
                    const float p0 = acc[mt][nt + 4][2 * half];
                    const float p1 = acc[mt][nt + 4][2 * half + 1];
                    const float lo0 = (a0 * cs0.x - p0 * cs0.y) * scale;
                    const float lo1 = (a1 * cs1.x - p1 * cs1.y) * scale;
                    const float hi0 = (p0 * cs0.x + a0 * cs0.y) * scale;
                    const float hi1 = (p1 * cs1.x + a1 * cs1.y) * scale;
                    *(__half2*)&dst[base + d]      = __floats2half2_rn(lo0, lo1);
                    *(__half2*)&dst[base + d + 32] = __floats2half2_rn(hi0, hi1);
                }
            }
        }
    }
}

// ---------------------------------------------------------------------------
// fp16 tensor-core flash attention (R13 direct form — no split-KV).
// Block = (128-row q tile, bh), 4 warps, 32 q rows/warp. Heavy blocks first.
// ---------------------------------------------------------------------------
#define AP 72
#define ATTN_SMEM ((128 * AP + 4 * 64 * AP) * 2)

__global__ void __launch_bounds__(128, 3)
attn_fp16_kernel()
{
    extern __shared__ __half sh[];
    __half* qs = sh;                         // [128][72]
    __half* kbuf[2] = { sh + 128 * AP, sh + 128 * AP + 2 * 64 * AP };
    __half* vbuf[2] = { sh + 128 * AP + 64 * AP, sh + 128 * AP + 3 * 64 * AP };

    const int qt = (T_ / 128 - 1) - blockIdx.x;   // heavy blocks first
    const int bh = blockIdx.y;
    const int tid = threadIdx.x;
    const int lane = tid & 31;
    const int w = tid >> 5;
    const int lrow = lane >> 2;
    const int lk = lane & 3;
    const int wrow = w * 32;

    const int a_row_off = lane & 15;
    const int a_col_off = (lane >> 4) * 8;
    const int b_row_off = (lane >> 4) * 8 + (lane & 7);
    const int b_col_off = ((lane >> 3) & 1) * 8;

    const __half* Qb = g_qh + ((size_t)bh * T_ + qt * 128) * DH_;
    const __half* Kb = g_kh + (size_t)bh * T_ * DH_;
    const __half* Vb = g_vh + (size_t)bh * T_ * DH_;

#pragma unroll
    for (int i = 0; i < 8; i++) {
        const int e = tid + i * 128;
        const int r = e >> 3;
        const int c = (e & 7) * 8;
        cp16(&qs[r * AP + c], &Qb[r * 64 + c]);
    }
#pragma unroll
    for (int i = 0; i < 4; i++) {
        const int e = tid + i * 128;
        const int r = e >> 3;
        const int c = (e & 7) * 8;
        cp16(&kbuf[0][r * AP + c], Kb + (size_t)r * 64 + c);
        cp16(&vbuf[0][r * AP + c], Vb + (size_t)r * 64 + c);
    }
    cp_commit();

    float m[2][2], l[2][2];
    float oacc[2][8][4];
#pragma unroll
    for (int mg = 0; mg < 2; mg++) {
        m[mg][0] = -1e30f; m[mg][1] = -1e30f;
        l[mg][0] = 0.f;    l[mg][1] = 0.f;
#pragma unroll
        for (int nt = 0; nt < 8; nt++)
#pragma unroll
            for (int i = 0; i < 4; i++) oacc[mg][nt][i] = 0.f;
    }

    const int ktmax = 2 * qt + 1;
    for (int kt = 0; kt <= ktmax; kt++) {
        const int s = kt & 1;
        cp_wait0();
        __syncthreads();

        if (kt < ktmax) {
#pragma unroll
            for (int i = 0; i < 4; i++) {
                const int e = tid + i * 128;
                const int r = e >> 3;
                const int c = (e & 7) * 8;
                cp16(&kbuf[s ^ 1][r * AP + c], Kb + (size_t)((kt + 1) * 64 + r) * 64 + c);
                cp16(&vbuf[s ^ 1][r * AP + c], Vb + (size_t)((kt + 1) * 64 + r) * 64 + c);
            }
            cp_commit();
        }

        const __half* ks = kbuf[s];
        const __half* vs = vbuf[s];

        float sacc[2][8][4];
#pragma unroll
        for (int mg = 0; mg < 2; mg++)
#pragma unroll
            for (int nt = 0; nt < 8; nt++)
#pragma unroll
                for (int i = 0; i < 4; i++) sacc[mg][nt][i] = 0.f;

#pragma unroll
        for (int kc = 0; kc < 4; kc++) {
            const int kh = kc * 16;
            unsigned af[2][4];
#pragma unroll
            for (int mg = 0; mg < 2; mg++)
                ldsm_x4(af[mg][0], af[mg][1], af[mg][2], af[mg][3],
                        &qs[(wrow + mg * 16 + a_row_off) * AP + kh + a_col_off]);
            unsigned bf[8][2];
#pragma unroll
            for (int ntp = 0; ntp < 4; ntp++) {
                unsigned r0, r1, r2, r3;
                ldsm_x4(r0, r1, r2, r3,
                        &ks[(ntp * 16 + b_row_off) * AP + kh + b_col_off]);
                bf[2 * ntp][0] = r0;     bf[2 * ntp][1] = r1;
                bf[2 * ntp + 1][0] = r2; bf[2 * ntp + 1][1] = r3;
            }
#pragma unroll
            for (int nt = 0; nt < 8; nt++)
#pragma unroll
                for (int mg = 0; mg < 2; mg++)
                    mma_f16(sacc[mg][nt], af[mg][0], af[mg][1], af[mg][2], af[mg][3],
                            bf[nt][0], bf[nt][1]);
        }

        if (kt * 64 + 63 > qt * 128 + wrow) {
#pragma unroll
            for (int mg = 0; mg < 2; mg++) {
                const int rg0 = qt * 128 + wrow + mg * 16 + lrow;
                const int rg1 = rg0 + 8;
#pragma unroll
                for (int nt = 0; nt < 8; nt++) {
                    const int cg = kt * 64 + nt * 8 + lk * 2;
                    if (cg > rg0)     sacc[mg][nt][0] = -1e30f;
                    if (cg + 1 > rg0) sacc[mg][nt][1] = -1e30f;
                    if (cg > rg1)     sacc[mg][nt][2] = -1e30f;
                    if (cg + 1 > rg1) sacc[mg][nt][3] = -1e30f;
                }
            }
        }

        unsigned pk01[2][8], pk23[2][8];
#pragma unroll
        for (int mg = 0; mg < 2; mg++) {
            float tm0 = -1e30f, tm1 = -1e30f;
#pragma unroll
            for (int nt = 0; nt < 8; nt++) {
                tm0 = fmaxf(tm0, fmaxf(sacc[mg][nt][0], sacc[mg][nt][1]));
                tm1 = fmaxf(tm1, fmaxf(sacc[mg][nt][2], sacc[mg][nt][3]));
            }
            tm0 = fmaxf(tm0, __shfl_xor_sync(0xffffffffu, tm0, 1));
            tm0 = fmaxf(tm0, __shfl_xor_sync(0xffffffffu, tm0, 2));
            tm1 = fmaxf(tm1, __shfl_xor_sync(0xffffffffu, tm1, 1));
            tm1 = fmaxf(tm1, __shfl_xor_sync(0xffffffffu, tm1, 2));

            const float mn0 = fmaxf(m[mg][0], tm0);
            const float mn1 = fmaxf(m[mg][1], tm1);
            const float corr0 = __expf(m[mg][0] - mn0);
            const float corr1 = __expf(m[mg][1] - mn1);
            m[mg][0] = mn0; m[mg][1] = mn1;

            float sum0 = 0.f, sum1 = 0.f;
#pragma unroll
            for (int nt = 0; nt < 8; nt++) {
                const float p00 = __expf(sacc[mg][nt][0] - mn0);
                const float p01 = __expf(sacc[mg][nt][1] - mn0);
                const float p10 = __expf(sacc[mg][nt][2] - mn1);
                const float p11 = __expf(sacc[mg][nt][3] - mn1);
                sum0 += p00 + p01;
                sum1 += p10 + p11;
                pk01[mg][nt] = pack_h2(p00, p01);
                pk23[mg][nt] = pack_h2(p10, p11);
            }
            sum0 += __shfl_xor_sync(0xffffffffu, sum0, 1);
            sum0 += __shfl_xor_sync(0xffffffffu, sum0, 2);
            sum1 += __shfl_xor_sync(0xffffffffu, sum1, 1);
            sum1 += __shfl_xor_sync(0xffffffffu, sum1, 2);
            l[mg][0] = l[mg][0] * corr0 + sum0;
            l[mg][1] = l[mg][1] * corr1 + sum1;

#pragma unroll
            for (int nt = 0; nt < 8; nt++) {
                oacc[mg][nt][0] *= corr0;
                oacc[mg][nt][1] *= corr0;
                oacc[mg][nt][2] *= corr1;
                oacc[mg][nt][3] *= corr1;
            }
        }

#pragma unroll
        for (int kc = 0; kc < 4; kc++) {
            const int g = lane >> 3;
            const int li = lane & 7;
            const int vrow = kc * 16 + (g & 1) * 8 + li;
#pragma unroll
            for (int ntp = 0; ntp < 4; ntp++) {
                const int vcol = ntp * 16 + (g >> 1) * 8;
                unsigned r0, r1, r2, r3;
                ldsm_x4_trans(r0, r1, r2, r3, &vs[vrow * AP + vcol]);
#pragma unroll
                for (int mg = 0; mg < 2; mg++) {
                    mma_f16(oacc[mg][ntp * 2],
                            pk01[mg][2 * kc], pk23[mg][2 * kc],
                            pk01[mg][2 * kc + 1], pk23[mg][2 * kc + 1], r0, r1);
                    mma_f16(oacc[mg][ntp * 2 + 1],
                            pk01[mg][2 * kc], pk23[mg][2 * kc],
                            pk01[mg][2 * kc + 1], pk23[mg][2 * kc + 1], r2, r3);
                }
            }
        }
    }

    const int b = bh >> 4;
    const int h = bh & (H_ - 1);
#pragma unroll
    for (int mg = 0; mg < 2; mg++) {
        const float il0 = 1.0f / l[mg][0];
        const float il1 = 1.0f / l[mg][1];
        const int t0 = qt * 128 + wrow + mg * 16 + lrow;
        const int t1 = t0 + 8;
        const size_t base0 = ((size_t)(b * T_ + t0)) * D_ + h * DH_;
        const size_t base1 = ((size_t)(b * T_ + t1)) * D_ + h * DH_;
#pragma unroll
        for (int nt = 0; nt < 8; nt++) {
            const int c0 = nt * 8 + lk * 2;
            *(__half2*)&g_attnh[base0 + c0] =
                __floats2half2_rn(oacc[mg][nt][0] * il0, oacc[mg][nt][1] * il0);
            *(__half2*)&g_attnh[base1 + c0] =
                __floats2half2_rn(oacc[mg][nt][2] * il1, oacc[mg][nt][3] * il1);
        }
    }
}

// ---------------------------------------------------------------------------
// kernel_launch
// ---------------------------------------------------------------------------
extern "C" void kernel_launch(void* const* d_in, const int* in_sizes, int n_in,
                              void* d_out, int out_size)
{
    (void)in_sizes; (void)n_in; (void)out_size;
    const float* x     = (const float*)d_in[0];
    const float* qkv_w = (const float*)d_in[2];
    const float* out_w = (const float*)d_in[3];
    const float* out_b = (const float*)d_in[4];
    float* out = (float*)d_out;

    void *p_xh, *p_w1t, *p_w2t, *p_attnh;
    cudaGetSymbolAddress(&p_xh, g_xh);
    cudaGetSymbolAddress(&p_w1t, g_w1t);
    cudaGetSymbolAddress(&p_w2t, g_w2t);
    cudaGetSymbolAddress(&p_attnh, g_attnh);

    cudaFuncSetAttribute(gemm_fp16,
                         cudaFuncAttributeMaxDynamicSharedMemorySize, GEMM_SMEM);
    cudaFuncSetAttribute(attn_fp16_kernel,
                         cudaFuncAttributeMaxDynamicSharedMemorySize, ATTN_SMEM);

    // 0) fused prep (x->fp16, both weight transposes, rope table)
    prep_kernel<<<PREP_BLOCKS, 256>>>(x, qkv_w, out_w);

    // 1) QKV projection with fused RoPE + scatter (mode 1)
    gemm_fp16<<<dim3((3 * D_) / 128, NROW / 128), 128, GEMM_SMEM>>>(
        (const __half*)p_xh, (const __half*)p_w1t, nullptr, nullptr,
        1, NROW, 3 * D_, D_);

    // 2) causal flash attention
    attn_fp16_kernel<<<dim3(T_ / 128, BH_), 128, ATTN_SMEM>>>();

    // 3) output projection + bias -> f32 (mode 0)
    gemm_fp16<<<dim3(D_ / 128, NROW / 128), 128, GEMM_SMEM>>>(
        (const __half*)p_attnh, (const __half*)p_w2t, out_b, out,
        0, NROW, D_, D_);
}

// round 16
// speedup vs baseline: 1.0999x; 1.0208x over previous
#include <cuda_runtime.h>
#include <cuda_fp16.h>
#include <math.h>

// Problem constants
#define B_ 2
#define T_ 2048
#define D_ 1024
#define H_ 16
#define DH_ 64
#define NROW (B_ * T_)        // 4096
#define BH_ (B_ * H_)         // 32

// ---------------------------------------------------------------------------
// Scratch
// ---------------------------------------------------------------------------
__device__ __half g_xh [(size_t)NROW * D_];             // fp16 x
__device__ __half g_w1t[(size_t)(3 * D_) * D_];         // fp16 qkv_w transposed [N][K]
__device__ __half g_w2t[(size_t)D_ * D_];               // fp16 out_w transposed [N][K]
__device__ __half g_qh[(size_t)BH_ * T_ * DH_];
__device__ __half g_kh[(size_t)BH_ * T_ * DH_];
__device__ __half g_vh[(size_t)BH_ * T_ * DH_];
__device__ __half g_attnh[(size_t)NROW * D_];           // [4096, 1024] fp16
__device__ float2 g_rt[(size_t)T_ * 32];                // rope (cos,sin) table

// ---------------------------------------------------------------------------
// helpers
// ---------------------------------------------------------------------------
__device__ __forceinline__ unsigned pack_h2(float a, float b) {
    __half2 h = __floats2half2_rn(a, b);
    return *(unsigned*)&h;
}
__device__ __forceinline__ void mma_f16(float* c,
                                        unsigned a0, unsigned a1, unsigned a2, unsigned a3,
                                        unsigned b0, unsigned b1) {
    asm volatile("mma.sync.aligned.m16n8k16.row.col.f32.f16.f16.f32 "
                 "{%0,%1,%2,%3}, {%4,%5,%6,%7}, {%8,%9}, {%0,%1,%2,%3};"
                 : "+f"(c[0]), "+f"(c[1]), "+f"(c[2]), "+f"(c[3])
                 : "r"(a0), "r"(a1), "r"(a2), "r"(a3), "r"(b0), "r"(b1));
}
__device__ __forceinline__ void cp16(void* smem, const void* gmem) {
    unsigned s = (unsigned)__cvta_generic_to_shared(smem);
    asm volatile("cp.async.cg.shared.global [%0], [%1], 16;" :: "r"(s), "l"(gmem));
}
__device__ __forceinline__ void cp_commit() { asm volatile("cp.async.commit_group;"); }
__device__ __forceinline__ void cp_wait0()  { asm volatile("cp.async.wait_group 0;"); }
__device__ __forceinline__ void cp_wait1()  { asm volatile("cp.async.wait_group 1;"); }

__device__ __forceinline__ void ldsm_x4(unsigned& r0, unsigned& r1,
                                        unsigned& r2, unsigned& r3, const void* p) {
    unsigned s = (unsigned)__cvta_generic_to_shared(p);
    asm volatile("ldmatrix.sync.aligned.m8n8.x4.shared.b16 {%0,%1,%2,%3}, [%4];"
                 : "=r"(r0), "=r"(r1), "=r"(r2), "=r"(r3) : "r"(s));
}
__device__ __forceinline__ void ldsm_x4_trans(unsigned& r0, unsigned& r1,
                                              unsigned& r2, unsigned& r3, const void* p) {
    unsigned s = (unsigned)__cvta_generic_to_shared(p);
    asm volatile("ldmatrix.sync.aligned.m8n8.x4.trans.shared.b16 {%0,%1,%2,%3}, [%4];"
                 : "=r"(r0), "=r"(r1), "=r"(r2), "=r"(r3) : "r"(s));
}

// ---------------------------------------------------------------------------
// fused prep kernel — one launch covers:
//   blocks [0, 4096)        : x f32 -> fp16            (1024 elems/block)
//   blocks [4096, 7168)     : qkv_w [K][N] -> w1t [N][K] fp16 (32x32 tiles)
//   blocks [7168, 8192)     : out_w -> w2t
//   blocks [8192, 8448)     : rope table
// ---------------------------------------------------------------------------
#define PREP_BLOCKS (4096 + 3072 + 1024 + 256)

__global__ void prep_kernel(const float* __restrict__ x,
                            const float* __restrict__ w1,
                            const float* __restrict__ w2)
{
    __shared__ float tile[32][33];
    const int bid = blockIdx.x;
    const int tid = threadIdx.x;

    if (bid < 4096) {
        const int i = (bid * 256 + tid) * 4;
        float4 v = *(const float4*)(x + i);
        *(__half2*)&g_xh[i]     = __floats2half2_rn(v.x, v.y);
        *(__half2*)&g_xh[i + 2] = __floats2half2_rn(v.z, v.w);
    } else if (bid < 8192) {
        const float* in;
        __half* out;
        int bx, by, N;
        if (bid < 7168) {
            const int b = bid - 4096;
            bx = b % 96; by = b / 96; in = w1; out = g_w1t; N = 3 * D_;
        } else {
            const int b = bid - 7168;
            bx = b % 32; by = b / 32; in = w2; out = g_w2t; N = D_;
        }
        const int K = D_;
        const int n0 = bx * 32;
        const int k0 = by * 32;
        const int tx = tid & 31;
        const int ty = tid >> 5;
#pragma unroll
        for (int j = 0; j < 4; j++)
            tile[ty + 8 * j][tx] = in[(size_t)(k0 + ty + 8 * j) * N + n0 + tx];
        __syncthreads();
#pragma unroll
        for (int j = 0; j < 4; j++)
            out[(size_t)(n0 + ty + 8 * j) * K + k0 + tx] =
                __float2half(tile[tx][ty + 8 * j]);
    } else {
        const int idx = (bid - 8192) * 256 + tid;
        const int t = idx >> 5;
        const int d2 = idx & 31;
        const float inv = __powf(10000.0f, -(float)d2 * (1.0f / 32.0f));
        float sn, cs;
        sincosf((float)t * inv, &sn, &cs);
        g_rt[idx] = make_float2(cs, sn);
    }
}

// ---------------------------------------------------------------------------
// fp16 GEMM: block 128x128, BK=64, 128 threads = 4 warps (2m x 2n),
// warp tile 64x64. 3-stage cp.async (wait_group 1 keeps next tile in flight).
// smem 108KB -> 2 CTAs/SM.
// mode 0: C(f32) = A@Bt + bias. mode 1: fused RoPE QKV scatter.
// ---------------------------------------------------------------------------
#define GP 72
#define GEMM_SMEM (3 * 2 * 128 * GP * 2)

__global__ void __launch_bounds__(128, 2)
gemm_fp16(const __half* __restrict__ A, const __half* __restrict__ Bt,
          const float* __restrict__ bias, float* __restrict__ C,
          int mode, int M, int N, int K)
{
    extern __shared__ __half sh[];
    // stage layout: [3][A 128*GP | B 128*GP]
    const int STG = 2 * 128 * GP;

    const int bm = blockIdx.y * 128;
    const int bn = blockIdx.x * 128;
    const int tid = threadIdx.x;
    const int lane = tid & 31;
    const int w = tid >> 5;
    const int lrow = lane >> 2;
    const int lk = lane & 3;
    const int wm = (w & 1) * 64;
    const int wn = (w >> 1) * 64;

    const int a_row_off = lane & 15;
    const int a_col_off = (lane >> 4) * 8;
    const int b_row_off = (lane >> 4) * 8 + (lane & 7);
    const int b_col_off = ((lane >> 3) & 1) * 8;

    float acc[4][8][4];
#pragma unroll
    for (int mt = 0; mt < 4; mt++)
#pragma unroll
        for (int nt = 0; nt < 8; nt++)
#pragma unroll
            for (int i = 0; i < 4; i++) acc[mt][nt][i] = 0.0f;

    const int ntiles = K / 64;

    // prologue: stage tiles 0 and 1
#pragma unroll
    for (int p = 0; p < 2; p++) {
        if (p < ntiles) {
            __half* Ad = sh + p * STG;
            __half* Bd = Ad + 128 * GP;
            const int kn = p * 64;
#pragma unroll
            for (int i = 0; i < 8; i++) {
                const int e = tid + i * 128;
                const int r = e >> 3;
                const int c = (e & 7) * 8;
                cp16(&Ad[r * GP + c], A + (size_t)(bm + r) * K + kn + c);
                cp16(&Bd[r * GP + c], Bt + (size_t)(bn + r) * K + kn + c);
            }
            cp_commit();
        }
    }

    for (int t = 0; t < ntiles; t++) {
        if (t + 1 < ntiles) cp_wait1(); else cp_wait0();
        __syncthreads();   // buf (t%3) consumers of iter t-3 done; staging of t visible

        if (t + 2 < ntiles) {
            const int kn = (t + 2) * 64;
            __half* Ad = sh + ((t + 2) % 3) * STG;
            __half* Bd = Ad + 128 * GP;
#pragma unroll
            for (int i = 0; i < 8; i++) {
                const int e = tid + i * 128;
                const int r = e >> 3;
                const int c = (e & 7) * 8;
                cp16(&Ad[r * GP + c], A + (size_t)(bm + r) * K + kn + c);
                cp16(&Bd[r * GP + c], Bt + (size_t)(bn + r) * K + kn + c);
            }
            cp_commit();
        }

        const __half* Ah = sh + (t % 3) * STG;
        const __half* Bh = Ah + 128 * GP;
#pragma unroll
        for (int kc = 0; kc < 4; kc++) {
            const int kh = kc * 16;
            unsigned af[4][4];
#pragma unroll
            for (int mt = 0; mt < 4; mt++)
                ldsm_x4(af[mt][0], af[mt][1], af[mt][2], af[mt][3],
                        &Ah[(wm + mt * 16 + a_row_off) * GP + kh + a_col_off]);
            unsigned bf[8][2];
#pragma unroll
            for (int ntp = 0; ntp < 4; ntp++) {
                unsigned r0, r1, r2, r3;
                ldsm_x4(r0, r1, r2, r3,
                        &Bh[(wn + ntp * 16 + b_row_off) * GP + kh + b_col_off]);
                bf[2 * ntp][0] = r0;     bf[2 * ntp][1] = r1;
                bf[2 * ntp + 1][0] = r2; bf[2 * ntp + 1][1] = r3;
            }
#pragma unroll
            for (int nt = 0; nt < 8; nt++)
#pragma unroll
                for (int mt = 0; mt < 4; mt++)
                    mma_f16(acc[mt][nt], af[mt][0], af[mt][1], af[mt][2], af[mt][3],
                            bf[nt][0], bf[nt][1]);
        }
    }

    // ------------------------- epilogue -------------------------
    if (mode == 0) {
#pragma unroll
        for (int mt = 0; mt < 4; mt++) {
            const int row0 = bm + wm + mt * 16 + lrow;
#pragma unroll
            for (int nt = 0; nt < 8; nt++) {
                const int col = bn + wn + nt * 8 + lk * 2;
                const float bx = bias ? bias[col] : 0.f;
                const float by = bias ? bias[col + 1] : 0.f;
                *(float2*)&C[(size_t)row0 * N + col] =
                    make_float2(acc[mt][nt][0] + bx, acc[mt][nt][1] + by);
                *(float2*)&C[(size_t)(row0 + 8) * N + col] =
                    make_float2(acc[mt][nt][2] + bx, acc[mt][nt][3] + by);
            }
        }
        return;
    }

    // mode 1: fused RoPE + scatter. Warp tile covers exactly one (s,h).
    const int colbase = bn + wn;
    const int sec = colbase >> 10;        // 0=q, 1=k, 2=v
    const int h = (colbase >> 6) & (H_ - 1);

    if (sec == 2) {
#pragma unroll
        for (int mt = 0; mt < 4; mt++) {
            const int row0 = bm + wm + mt * 16 + lrow;
#pragma unroll
            for (int half = 0; half < 2; half++) {
                const int row = row0 + 8 * half;
                const int b = row >> 11;
                const int tt = row & (T_ - 1);
                const size_t base = ((size_t)(b * H_ + h) * T_ + tt) * DH_;
#pragma unroll
                for (int nt = 0; nt < 8; nt++) {
                    const int d = nt * 8 + lk * 2;
                    *(__half2*)&g_vh[base + d] =
                        __floats2half2_rn(acc[mt][nt][2 * half], acc[mt][nt][2 * half + 1]);
                }
            }
        }
    } else {
        __half* dst = (sec == 0) ? g_qh : g_kh;
        const float scale = (sec == 0) ? 0.125f : 1.0f;
#pragma unroll
        for (int mt = 0; mt < 4; mt++) {
            const int row0 = bm + wm + mt * 16 + lrow;
#pragma unroll
            for (int half = 0; half < 2; half++) {
                const int row = row0 + 8 * half;
                const int b = row >> 11;
                const int tt = row & (T_ - 1);
                const size_t base = ((size_t)(b * H_ + h) * T_ + tt) * DH_;
#pragma unroll
                for (int nt = 0; nt < 4; nt++) {
                    const int d = nt * 8 + lk * 2;
                    const float2 cs0 = g_rt[tt * 32 + d];
                    const float2 cs1 = g_rt[tt * 32 + d + 1];
                    const float a0 = acc[mt][nt][2 * half];
                    const float a1 = acc[mt][nt][2 * half + 1];
                    const float p0 = acc[mt][nt + 4][2 * half];
                    const float p1 = acc[mt][nt + 4][2 * half + 1];
                    const float lo0 = (a0 * cs0.x - p0 * cs0.y) * scale;
                    const float lo1 = (a1 * cs1.x - p1 * cs1.y) * scale;
                    const float hi0 = (p0 * cs0.x + a0 * cs0.y) * scale;
                    const float hi1 = (p1 * cs1.x + a1 * cs1.y) * scale;
                    *(__half2*)&dst[base + d]      = __floats2half2_rn(lo0, lo1);
                    *(__half2*)&dst[base + d + 32] = __floats2half2_rn(hi0, hi1);
                }
            }
        }
    }
}

// ---------------------------------------------------------------------------
// fp16 tensor-core flash attention (unchanged from R15 best).
// ---------------------------------------------------------------------------
#define AP 72
#define ATTN_SMEM ((128 * AP + 4 * 64 * AP) * 2)

__global__ void __launch_bounds__(128, 3)
attn_fp16_kernel()
{
    extern __shared__ __half sh[];
    __half* qs = sh;                         // [128][72]
    __half* kbuf[2] = { sh + 128 * AP, sh + 128 * AP + 2 * 64 * AP };
    __half* vbuf[2] = { sh + 128 * AP + 64 * AP, sh + 128 * AP + 3 * 64 * AP };

    const int qt = (T_ / 128 - 1) - blockIdx.x;   // heavy blocks first
    const int bh = blockIdx.y;
    const int tid = threadIdx.x;
    const int lane = tid & 31;
    const int w = tid >> 5;
    const int lrow = lane >> 2;
    const int lk = lane & 3;
    const int wrow = w * 32;

    const int a_row_off = lane & 15;
    const int a_col_off = (lane >> 4) * 8;
    const int b_row_off = (lane >> 4) * 8 + (lane & 7);
    const int b_col_off = ((lane >> 3) & 1) * 8;

    const __half* Qb = g_qh + ((size_t)bh * T_ + qt * 128) * DH_;
    const __half* Kb = g_kh + (size_t)bh * T_ * DH_;
    const __half* Vb = g_vh + (size_t)bh * T_ * DH_;

#pragma unroll
    for (int i = 0; i < 8; i++) {
        const int e = tid + i * 128;
        const int r = e >> 3;
        const int c = (e & 7) * 8;
        cp16(&qs[r * AP + c], &Qb[r * 64 + c]);
    }
#pragma unroll
    for (int i = 0; i < 4; i++) {
        const int e = tid + i * 128;
        const int r = e >> 3;
        const int c = (e & 7) * 8;
        cp16(&kbuf[0][r * AP + c], Kb + (size_t)r * 64 + c);
        cp16(&vbuf[0][r * AP + c], Vb + (size_t)r * 64 + c);
    }
    cp_commit();

    float m[2][2], l[2][2];
    float oacc[2][8][4];
#pragma unroll
    for (int mg = 0; mg < 2; mg++) {
        m[mg][0] = -1e30f; m[mg][1] = -1e30f;
        l[mg][0] = 0.f;    l[mg][1] = 0.f;
#pragma unroll
        for (int nt = 0; nt < 8; nt++)
#pragma unroll
            for (int i = 0; i < 4; i++) oacc[mg][nt][i] = 0.f;
    }

    const int ktmax = 2 * qt + 1;
    for (int kt = 0; kt <= ktmax; kt++) {
        const int s = kt & 1;
        cp_wait0();
        __syncthreads();

        if (kt < ktmax) {
#pragma unroll
            for (int i = 0; i < 4; i++) {
                const int e = tid + i * 128;
                const int r = e >> 3;
                const int c = (e & 7) * 8;
                cp16(&kbuf[s ^ 1][r * AP + c], Kb + (size_t)((kt + 1) * 64 + r) * 64 + c);
                cp16(&vbuf[s ^ 1][r * AP + c], Vb + (size_t)((kt + 1) * 64 + r) * 64 + c);
            }
            cp_commit();
        }

        const __half* ks = kbuf[s];
        const __half* vs = vbuf[s];

        float sacc[2][8][4];
#pragma unroll
        for (int mg = 0; mg < 2; mg++)
#pragma unroll
            for (int nt = 0; nt < 8; nt++)
#pragma unroll
                for (int i = 0; i < 4; i++) sacc[mg][nt][i] = 0.f;

#pragma unroll
        for (int kc = 0; kc < 4; kc++) {
            const int kh = kc * 16;
            unsigned af[2][4];
#pragma unroll
            for (int mg = 0; mg < 2; mg++)
                ldsm_x4(af[mg][0], af[mg][1], af[mg][2], af[mg][3],
                        &qs[(wrow + mg * 16 + a_row_off) * AP + kh + a_col_off]);
            unsigned bf[8][2];
#pragma unroll
            for (int ntp = 0; ntp < 4; ntp++) {
                unsigned r0, r1, r2, r3;
                ldsm_x4(r0, r1, r2, r3,
                        &ks[(ntp * 16 + b_row_off) * AP + kh + b_col_off]);
                bf[2 * ntp][0] = r0;     bf[2 * ntp][1] = r1;
                bf[2 * ntp + 1][0] = r2; bf[2 * ntp + 1][1] = r3;
            }
#pragma unroll
            for (int nt = 0; nt < 8; nt++)
#pragma unroll
                for (int mg = 0; mg < 2; mg++)
                    mma_f16(sacc[mg][nt], af[mg][0], af[mg][1], af[mg][2], af[mg][3],
                            bf[nt][0], bf[nt][1]);
        }

        if (kt * 64 + 63 > qt * 128 + wrow) {
#pragma unroll
            for (int mg = 0; mg < 2; mg++) {
                const int rg0 = qt * 128 + wrow + mg * 16 + lrow;
                const int rg1 = rg0 + 8;
#pragma unroll
                for (int nt = 0; nt < 8; nt++) {
                    const int cg = kt * 64 + nt * 8 + lk * 2;
                    if (cg > rg0)     sacc[mg][nt][0] = -1e30f;
                    if (cg + 1 > rg0) sacc[mg][nt][1] = -1e30f;
                    if (cg > rg1)     sacc[mg][nt][2] = -1e30f;
                    if (cg + 1 > rg1) sacc[mg][nt][3] = -1e30f;
                }
            }
        }

        unsigned pk01[2][8], pk23[2][8];
#pragma unroll
        for (int mg = 0; mg < 2; mg++) {
            float tm0 = -1e30f, tm1 = -1e30f;
#pragma unroll
            for (int nt = 0; nt < 8; nt++) {
                tm0 = fmaxf(tm0, fmaxf(sacc[mg][nt][0], sacc[mg][nt][1]));
                tm1 = fmaxf(tm1, fmaxf(sacc[mg][nt][2], sacc[mg][nt][3]));
            }
            tm0 = fmaxf(tm0, __shfl_xor_sync(0xffffffffu, tm0, 1));
            tm0 = fmaxf(tm0, __shfl_xor_sync(0xffffffffu, tm0, 2));
            tm1 = fmaxf(tm1, __shfl_xor_sync(0xffffffffu, tm1, 1));
            tm1 = fmaxf(tm1, __shfl_xor_sync(0xffffffffu, tm1, 2));

            const float mn0 = fmaxf(m[mg][0], tm0);
            const float mn1 = fmaxf(m[mg][1], tm1);
            const float corr0 = __expf(m[mg][0] - mn0);
            const float corr1 = __expf(m[mg][1] - mn1);
            m[mg][0] = mn0; m[mg][1] = mn1;

            float sum0 = 0.f, sum1 = 0.f;
#pragma unroll
            for (int nt = 0; nt < 8; nt++) {
                const float p00 = __expf(sacc[mg][nt][0] - mn0);
                const float p01 = __expf(sacc[mg][nt][1] - mn0);
                const float p10 = __expf(sacc[mg][nt][2] - mn1);
                const float p11 = __expf(sacc[mg][nt][3] - mn1);
                sum0 += p00 + p01;
                sum1 += p10 + p11;
                pk01[mg][nt] = pack_h2(p00, p01);
                pk23[mg][nt] = pack_h2(p10, p11);
            }
            sum0 += __shfl_xor_sync(0xffffffffu, sum0, 1);
            sum0 += __shfl_xor_sync(0xffffffffu, sum0, 2);
            sum1 += __shfl_xor_sync(0xffffffffu, sum1, 1);
            sum1 += __shfl_xor_sync(0xffffffffu, sum1, 2);
            l[mg][0] = l[mg][0] * corr0 + sum0;
            l[mg][1] = l[mg][1] * corr1 + sum1;

#pragma unroll
            for (int nt = 0; nt < 8; nt++) {
                oacc[mg][nt][0] *= corr0;
                oacc[mg][nt][1] *= corr0;
                oacc[mg][nt][2] *= corr1;
                oacc[mg][nt][3] *= corr1;
            }
        }

#pragma unroll
        for (int kc = 0; kc < 4; kc++) {
            const int g = lane >> 3;
            const int li = lane & 7;
            const int vrow = kc * 16 + (g & 1) * 8 + li;
#pragma unroll
            for (int ntp = 0; ntp < 4; ntp++) {
                const int vcol = ntp * 16 + (g >> 1) * 8;
                unsigned r0, r1, r2, r3;
                ldsm_x4_trans(r0, r1, r2, r3, &vs[vrow * AP + vcol]);
#pragma unroll
                for (int mg = 0; mg < 2; mg++) {
                    mma_f16(oacc[mg][ntp * 2],
                            pk01[mg][2 * kc], pk23[mg][2 * kc],
                            pk01[mg][2 * kc + 1], pk23[mg][2 * kc + 1], r0, r1);
                    mma_f16(oacc[mg][ntp * 2 + 1],
                            pk01[mg][2 * kc], pk23[mg][2 * kc],
                            pk01[mg][2 * kc + 1], pk23[mg][2 * kc + 1], r2, r3);
                }
            }
        }
    }

    const int b = bh >> 4;
    const int h = bh & (H_ - 1);
#pragma unroll
    for (int mg = 0; mg < 2; mg++) {
        const float il0 = 1.0f / l[mg][0];
        const float il1 = 1.0f / l[mg][1];
        const int t0 = qt * 128 + wrow + mg * 16 + lrow;
        const int t1 = t0 + 8;
        const size_t base0 = ((size_t)(b * T_ + t0)) * D_ + h * DH_;
        const size_t base1 = ((size_t)(b * T_ + t1)) * D_ + h * DH_;
#pragma unroll
        for (int nt = 0; nt < 8; nt++) {
            const int c0 = nt * 8 + lk * 2;
            *(__half2*)&g_attnh[base0 + c0] =
                __floats2half2_rn(oacc[mg][nt][0] * il0, oacc[mg][nt][1] * il0);
            *(__half2*)&g_attnh[base1 + c0] =
                __floats2half2_rn(oacc[mg][nt][2] * il1, oacc[mg][nt][3] * il1);
        }
    }
}

// ---------------------------------------------------------------------------
// kernel_launch
// ---------------------------------------------------------------------------
extern "C" void kernel_launch(void* const* d_in, const int* in_sizes, int n_in,
                              void* d_out, int out_size)
{
    (void)in_sizes; (void)n_in; (void)out_size;
    const float* x     = (const float*)d_in[0];
    const float* qkv_w = (const float*)d_in[2];
    const float* out_w = (const float*)d_in[3];
    const float* out_b = (const float*)d_in[4];
    float* out = (float*)d_out;

    void *p_xh, *p_w1t, *p_w2t, *p_attnh;
    cudaGetSymbolAddress(&p_xh, g_xh);
    cudaGetSymbolAddress(&p_w1t, g_w1t);
    cudaGetSymbolAddress(&p_w2t, g_w2t);
    cudaGetSymbolAddress(&p_attnh, g_attnh);

    cudaFuncSetAttribute(gemm_fp16,
                         cudaFuncAttributeMaxDynamicSharedMemorySize, GEMM_SMEM);
    cudaFuncSetAttribute(attn_fp16_kernel,
                         cudaFuncAttributeMaxDynamicSharedMemorySize, ATTN_SMEM);

    // 0) fused prep
    prep_kernel<<<PREP_BLOCKS, 256>>>(x, qkv_w, out_w);

    // 1) QKV projection with fused RoPE + scatter (mode 1)
    gemm_fp16<<<dim3((3 * D_) / 128, NROW / 128), 128, GEMM_SMEM>>>(
        (const __half*)p_xh, (const __half*)p_w1t, nullptr, nullptr,
        1, NROW, 3 * D_, D_);

    // 2) causal flash attention
    attn_fp16_kernel<<<dim3(T_ / 128, BH_), 128, ATTN_SMEM>>>();

    // 3) output projection + bias -> f32 (mode 0)
    gemm_fp16<<<dim3(D_ / 128, NROW / 128), 128, GEMM_SMEM>>>(
        (const __half*)p_attnh, (const __half*)p_w2t, out_b, out,
        0, NROW, D_, D_);
}